// round 2
// baseline (speedup 1.0000x reference)
#include <cuda_runtime.h>
#include <math.h>
#include <stdint.h>

// Problem constants
#define BB   16
#define CC   32
#define TT   62
#define VV   19
#define DD   128
#define HH   8
#define HDm  256          // hidden dim of FFN / emb
#define NBT  (BB*TT)      // 992
#define NTOK (NBT*VV)     // 18848
#define NPAIR (VV*VV)     // 361

// ---------------- scratch buffers (device globals; no allocation allowed) ----------------
__device__ float d_p   [NTOK*CC];     // p  [bt, v, c]
__device__ float d_y   [NTOK*DD];     // running activation (flat [tokens,128])
__device__ float d_e   [NTOK*HDm];    // e = p @ W_emb^T
__device__ float d_bias[NBT*NPAIR*HH];// attn bias [bt, i, j, h]
__device__ float d_qkv [NTOK*384];
__device__ float d_a   [NTOK*DD];
__device__ float d_y1  [NTOK*DD];
__device__ float d_h   [NTOK*HDm];
__device__ float d_f   [NTOK*DD];
__device__ float d_mem [NTOK*DD];
__device__ float d_pe  [TT*DD];

// ---------------- p builder: pose [B,C,T,V] -> p [B,T,V,C] ----------------
__global__ void build_p_kernel(const float* __restrict__ pose) {
    int idx = blockIdx.x * 256 + threadIdx.x;
    if (idx >= NTOK * CC) return;
    int c  = idx & 31;
    int v  = (idx >> 5) % VV;
    int bt = idx / (CC * VV);
    int b = bt / TT, t = bt % TT;
    d_p[idx] = pose[(((size_t)b * CC + c) * TT + t) * VV + v];
}

// ---------------- positional encoding ----------------
__global__ void build_pe_kernel() {
    int t = blockIdx.x, c = threadIdx.x;
    int i2 = c & ~1;
    float div = expf((float)i2 * (-9.210340371976184f / 128.f)); // -ln(10000)/128
    float ang = (float)t * div;
    d_pe[t * DD + c] = (c & 1) ? cosf(ang) : sinf(ang);
}

// ---------------- generic fp32 GEMM: C = act(A[M,K] @ W[N,K]^T + bias) ----------------
// act: 0 = none, 1 = relu, 2 = leakyrelu(0.01)
// act: 3 = "pe epilogue": v += pe[row%62][col]; write C (=y) and C2 (=mem)
__global__ __launch_bounds__(256)
void gemm_kernel(const float* __restrict__ A, const float* __restrict__ W,
                 const float* __restrict__ bias, float* __restrict__ C,
                 float* __restrict__ C2,
                 int M, int N, int K, int act)
{
    __shared__ float As[16][64];
    __shared__ float Bs[16][64];
    int tid = threadIdx.x;
    int m0 = blockIdx.x * 64;
    int n0 = blockIdx.y * 64;
    int tx = tid & 15, ty = tid >> 4;
    int lr = tid >> 2;   // 0..63 tile row
    int lq = tid & 3;    // float4 slot 0..3
    float acc[4][4] = {};

    for (int k0 = 0; k0 < K; k0 += 16) {
        float4 av = make_float4(0.f, 0.f, 0.f, 0.f);
        int arow = m0 + lr;
        if (arow < M) av = *(const float4*)(A + (size_t)arow * K + k0 + lq * 4);
        As[lq*4+0][lr] = av.x; As[lq*4+1][lr] = av.y;
        As[lq*4+2][lr] = av.z; As[lq*4+3][lr] = av.w;
        float4 wv = *(const float4*)(W + (size_t)(n0 + lr) * K + k0 + lq * 4);
        Bs[lq*4+0][lr] = wv.x; Bs[lq*4+1][lr] = wv.y;
        Bs[lq*4+2][lr] = wv.z; Bs[lq*4+3][lr] = wv.w;
        __syncthreads();
        #pragma unroll
        for (int k = 0; k < 16; k++) {
            float am[4], bn[4];
            #pragma unroll
            for (int i = 0; i < 4; i++) am[i] = As[k][ty*4+i];
            #pragma unroll
            for (int j = 0; j < 4; j++) bn[j] = Bs[k][tx*4+j];
            #pragma unroll
            for (int i = 0; i < 4; i++)
                #pragma unroll
                for (int j = 0; j < 4; j++) acc[i][j] += am[i] * bn[j];
        }
        __syncthreads();
    }
    #pragma unroll
    for (int i = 0; i < 4; i++) {
        int row = m0 + ty*4 + i;
        if (row >= M) continue;
        #pragma unroll
        for (int j = 0; j < 4; j++) {
            int col = n0 + tx*4 + j;
            float v = acc[i][j];
            if (bias) v += bias[col];
            if (act == 1) v = fmaxf(v, 0.f);
            else if (act == 2) v = (v >= 0.f) ? v : 0.01f * v;
            else if (act == 3) v += d_pe[(row % TT) * DD + col];
            C[(size_t)row * N + col] = v;
            if (act == 3) C2[(size_t)row * N + col] = v;
        }
    }
}

// ---------------- fused pairwise bias: bias[bt,i,j,g] = (1/sqrt(8)) * sum_k Wb[g,k]*prelu(e_j[k]-e_i[k]) ----
__global__ __launch_bounds__(256)
void bias_kernel(const float* __restrict__ E, const float* __restrict__ WB,
                 const float* __restrict__ prelu_a, int iter, float* __restrict__ OUT)
{
    __shared__ float es[VV * HDm];   // 19*256
    __shared__ float wb[HH * HDm];   // 8*256
    int bt = blockIdx.x;
    int tid = threadIdx.x;
    for (int idx = tid; idx < VV * HDm; idx += 256)
        es[idx] = E[((size_t)bt * VV) * HDm + idx];
    for (int idx = tid; idx < HH * HDm; idx += 256)
        wb[idx] = WB[idx];
    float aP = prelu_a[iter];
    __syncthreads();

    int warp = tid >> 5, lane = tid & 31;
    for (int pr = warp; pr < NPAIR; pr += 8) {
        int vi = pr / VV, vj = pr % VV;
        float acc[8] = {0,0,0,0,0,0,0,0};
        #pragma unroll
        for (int u = 0; u < 8; u++) {
            int k = u * 32 + lane;
            float hv = es[vj * HDm + k] - es[vi * HDm + k];
            hv = (hv >= 0.f) ? hv : aP * hv;
            #pragma unroll
            for (int g = 0; g < 8; g++) acc[g] += hv * wb[g * HDm + k];
        }
        #pragma unroll
        for (int g = 0; g < 8; g++)
            #pragma unroll
            for (int o = 16; o; o >>= 1)
                acc[g] += __shfl_xor_sync(0xffffffffu, acc[g], o);
        if (lane == 0) {
            float* o = OUT + (((size_t)bt * VV + vi) * VV + vj) * HH;
            #pragma unroll
            for (int g = 0; g < 8; g++) o[g] = acc[g] * 0.3535533906f;
        }
    }
}

// ---------------- graph attention (N=19, per-head bias) ----------------
__global__ __launch_bounds__(256)
void graph_attn_kernel(const float* __restrict__ QKV, const float* __restrict__ BIAS,
                       float* __restrict__ OUT)
{
    __shared__ float qs[VV * DD];      // [n][c]
    __shared__ float ks[DD * VV];      // [c][j]  stride 19 (conflict-free)
    __shared__ float vs[DD * VV];
    int bt = blockIdx.x;
    int tid = threadIdx.x;
    for (int idx = tid; idx < VV * DD; idx += 256) {
        int n = idx >> 7, c = idx & 127;
        const float* row = QKV + (size_t)(bt * VV + n) * 384;
        qs[idx] = row[c];
        ks[c * VV + n] = row[128 + c];
        vs[c * VV + n] = row[256 + c];
    }
    __syncthreads();
    int h = tid >> 5, lane = tid & 31;
    for (int i = 0; i < VV; i++) {
        float sc = -1e30f;
        if (lane < VV) {
            float acc = 0.f;
            #pragma unroll
            for (int c = 0; c < 16; c++)
                acc += qs[i * DD + h * 16 + c] * ks[(h * 16 + c) * VV + lane];
            sc = acc * 0.25f + BIAS[(((size_t)bt * VV + i) * VV + lane) * HH + h];
        }
        float mx = sc;
        #pragma unroll
        for (int o = 16; o; o >>= 1) mx = fmaxf(mx, __shfl_xor_sync(0xffffffffu, mx, o));
        float ev = (lane < VV) ? __expf(sc - mx) : 0.f;
        float sum = ev;
        #pragma unroll
        for (int o = 16; o; o >>= 1) sum += __shfl_xor_sync(0xffffffffu, sum, o);
        float aj = ev / sum;
        float o_acc = 0.f;
        int cc = lane & 15;
        #pragma unroll
        for (int j = 0; j < VV; j++) {
            float aw = __shfl_sync(0xffffffffu, aj, j);
            o_acc += aw * vs[(h * 16 + cc) * VV + j];
        }
        if (lane < 16) OUT[(size_t)(bt * VV + i) * DD + h * 16 + lane] = o_acc;
    }
}

// ---------------- temporal attention (N=62, no bias) ----------------
__global__ __launch_bounds__(128)
void temporal_attn_kernel(const float* __restrict__ QKV, float* __restrict__ OUT)
{
    __shared__ float ks[16 * 65];
    __shared__ float vs[16 * 65];
    int bn = blockIdx.x, h = blockIdx.y;
    int tid = threadIdx.x;
    for (int idx = tid; idx < 16 * 64; idx += 128) {
        int c = idx >> 6, n = idx & 63;
        float kv = 0.f, vv = 0.f;
        if (n < TT) {
            const float* row = QKV + (size_t)(bn * TT + n) * 384 + h * 16 + c;
            kv = row[128];
            vv = row[256];
        }
        ks[c * 65 + n] = kv;
        vs[c * 65 + n] = vv;
    }
    __syncthreads();
    int warp = tid >> 5, lane = tid & 31;
    for (int i = warp; i < TT; i += 4) {
        float q = (lane < 16) ? QKV[(size_t)(bn * TT + i) * 384 + h * 16 + lane] : 0.f;
        float s0 = 0.f, s1 = 0.f;
        #pragma unroll
        for (int c = 0; c < 16; c++) {
            float qc = __shfl_sync(0xffffffffu, q, c);
            s0 += qc * ks[c * 65 + lane];
            s1 += qc * ks[c * 65 + lane + 32];
        }
        s0 *= 0.25f; s1 *= 0.25f;
        bool v1 = (lane + 32) < TT;
        float mx = fmaxf(s0, v1 ? s1 : -1e30f);
        #pragma unroll
        for (int o = 16; o; o >>= 1) mx = fmaxf(mx, __shfl_xor_sync(0xffffffffu, mx, o));
        float e0 = __expf(s0 - mx);
        float e1 = v1 ? __expf(s1 - mx) : 0.f;
        float sum = e0 + e1;
        #pragma unroll
        for (int o = 16; o; o >>= 1) sum += __shfl_xor_sync(0xffffffffu, sum, o);
        float inv = 1.f / sum;
        e0 *= inv; e1 *= inv;
        float o_acc = 0.f;
        int cc = lane & 15;
        #pragma unroll
        for (int j = 0; j < 32; j++) {
            float aw = __shfl_sync(0xffffffffu, e0, j);
            o_acc += aw * vs[cc * 65 + j];
        }
        #pragma unroll
        for (int j = 32; j < TT; j++) {
            float aw = __shfl_sync(0xffffffffu, e1, j - 32);
            o_acc += aw * vs[cc * 65 + j];
        }
        if (lane < 16) OUT[(size_t)(bn * TT + i) * DD + h * 16 + lane] = o_acc;
    }
}

// ---------------- LayerNorm: out = LN(X + R) * g + b   (D=128, one warp/row) ----------------
__global__ __launch_bounds__(256)
void ln_kernel(const float* __restrict__ X, const float* __restrict__ R,
               const float* __restrict__ g, const float* __restrict__ b,
               float* __restrict__ OUT)
{
    int warp = threadIdx.x >> 5, lane = threadIdx.x & 31;
    int row = blockIdx.x * 8 + warp;
    if (row >= NTOK) return;
    const float* x = X + (size_t)row * DD;
    const float* r = R + (size_t)row * DD;
    float v[4];
    #pragma unroll
    for (int u = 0; u < 4; u++) v[u] = x[lane + u * 32] + r[lane + u * 32];
    float s = v[0] + v[1] + v[2] + v[3];
    #pragma unroll
    for (int o = 16; o; o >>= 1) s += __shfl_xor_sync(0xffffffffu, s, o);
    float m = s * (1.f / 128.f);
    float sv = 0.f;
    #pragma unroll
    for (int u = 0; u < 4; u++) { float dlt = v[u] - m; sv += dlt * dlt; }
    #pragma unroll
    for (int o = 16; o; o >>= 1) sv += __shfl_xor_sync(0xffffffffu, sv, o);
    float rinv = rsqrtf(sv * (1.f / 128.f) + 1e-5f);
    #pragma unroll
    for (int u = 0; u < 4; u++) {
        int c = lane + u * 32;
        OUT[(size_t)row * DD + c] = (v[u] - m) * rinv * g[c] + b[c];
    }
}

// ---------------- elementwise helper ----------------
__global__ void add_mem_kernel() {
    int idx = blockIdx.x * 256 + threadIdx.x;
    if (idx >= NTOK * DD) return;
    d_y[idx] = d_a[idx] + d_mem[idx];
}

// ---------------- host launcher ----------------
static void GEMM(const float* A, const float* W, const float* bias, float* C,
                 int M, int N, int K, int act, float* C2 = nullptr)
{
    dim3 grid((M + 63) / 64, N / 64);
    gemm_kernel<<<grid, 256>>>(A, W, bias, C, C2, M, N, K, act);
}

extern "C" void kernel_launch(void* const* d_in, const int* in_sizes, int n_in,
                              void* d_out, int out_size)
{
    const float* pose    = (const float*)d_in[0];
    const float* W_pose  = (const float*)d_in[1];
    const float* W_emb   = (const float*)d_in[2];
    const float* prelu_a = (const float*)d_in[3];
    const float* W_bias  = (const float*)d_in[4];
    const float* gWqkv   = (const float*)d_in[5];
    const float* gbqkv   = (const float*)d_in[6];
    const float* gWo     = (const float*)d_in[7];
    const float* gbo     = (const float*)d_in[8];
    const float* gln1g   = (const float*)d_in[9];
    const float* gln1b   = (const float*)d_in[10];
    const float* gW1     = (const float*)d_in[11];
    const float* gb1     = (const float*)d_in[12];
    const float* gW2     = (const float*)d_in[13];
    const float* gb2     = (const float*)d_in[14];
    const float* gln2g   = (const float*)d_in[15];
    const float* gln2b   = (const float*)d_in[16];
    const float* deW     = (const float*)d_in[17];
    const float* deb     = (const float*)d_in[18];
    const float* tWqkv   = (const float*)d_in[19];
    const float* tbqkv   = (const float*)d_in[20];
    const float* tWo     = (const float*)d_in[21];
    const float* tbo     = (const float*)d_in[22];
    const float* tln1g   = (const float*)d_in[23];
    const float* tln1b   = (const float*)d_in[24];
    const float* tW1     = (const float*)d_in[25];
    const float* tb1     = (const float*)d_in[26];
    const float* tW2     = (const float*)d_in[27];
    const float* tb2     = (const float*)d_in[28];
    const float* tln2g   = (const float*)d_in[29];
    const float* tln2b   = (const float*)d_in[30];
    const float* W_out   = (const float*)d_in[31];
    float* out = (float*)d_out;

    float *p_, *y_, *e_, *bias_, *qkv_, *a_, *y1_, *h_, *f_, *mem_;
    cudaGetSymbolAddress((void**)&p_,    d_p);
    cudaGetSymbolAddress((void**)&y_,    d_y);
    cudaGetSymbolAddress((void**)&e_,    d_e);
    cudaGetSymbolAddress((void**)&bias_, d_bias);
    cudaGetSymbolAddress((void**)&qkv_,  d_qkv);
    cudaGetSymbolAddress((void**)&a_,    d_a);
    cudaGetSymbolAddress((void**)&y1_,   d_y1);
    cudaGetSymbolAddress((void**)&h_,    d_h);
    cudaGetSymbolAddress((void**)&f_,    d_f);
    cudaGetSymbolAddress((void**)&mem_,  d_mem);

    build_p_kernel<<<(NTOK * CC + 255) / 256, 256>>>(pose);
    build_pe_kernel<<<TT, DD>>>();
    // y0 = p @ W_pose^T
    GEMM(p_, W_pose, nullptr, y_, NTOK, DD, CC, 0);

    for (int it = 0; it < 2; it++) {
        // ---- pairwise bias (linear-in-diff trick) ----
        GEMM(p_, W_emb + (size_t)it * HDm * CC, nullptr, e_, NTOK, HDm, CC, 0);
        bias_kernel<<<NBT, 256>>>(e_, W_bias + (size_t)it * HH * HDm, prelu_a, it, bias_);

        // ---- graph encoder block (rows = bt*19+v) ----
        GEMM(y_, gWqkv + (size_t)it * 3 * DD * DD, gbqkv + (size_t)it * 3 * DD,
             qkv_, NTOK, 384, DD, 0);
        graph_attn_kernel<<<NBT, 256>>>(qkv_, bias_, a_);
        GEMM(a_, gWo + (size_t)it * DD * DD, gbo + (size_t)it * DD, f_, NTOK, DD, DD, 0);
        ln_kernel<<<(NTOK + 7) / 8, 256>>>(f_, y_, gln1g + it * DD, gln1b + it * DD, y1_);
        GEMM(y1_, gW1 + (size_t)it * HDm * DD, gb1 + (size_t)it * HDm, h_, NTOK, HDm, DD, 1);
        GEMM(h_, gW2 + (size_t)it * DD * HDm, gb2 + (size_t)it * DD, f_, NTOK, DD, HDm, 0);
        ln_kernel<<<(NTOK + 7) / 8, 256>>>(f_, y1_, gln2g + it * DD, gln2b + it * DD, a_);
        // de linear, fused with positional-encoding add; writes y and mem
        // (reinterpret [B,T,V,D] flat -> [B*V, T, D] is a no-op on flat memory)
        GEMM(a_, deW + (size_t)it * DD * DD, deb + (size_t)it * DD, y_, NTOK, DD, DD, 3, mem_);

        // ---- temporal encoder block (rows = m*62+t, same flat buffer) ----
        GEMM(y_, tWqkv + (size_t)it * 3 * DD * DD, tbqkv + (size_t)it * 3 * DD,
             qkv_, NTOK, 384, DD, 0);
        {
            dim3 grid(BB * VV, HH);
            temporal_attn_kernel<<<grid, 128>>>(qkv_, a_);
        }
        GEMM(a_, tWo + (size_t)it * DD * DD, tbo + (size_t)it * DD, f_, NTOK, DD, DD, 0);
        ln_kernel<<<(NTOK + 7) / 8, 256>>>(f_, y_, tln1g + it * DD, tln1b + it * DD, y1_);
        GEMM(y1_, tW1 + (size_t)it * HDm * DD, tb1 + (size_t)it * HDm, h_, NTOK, HDm, DD, 1);
        GEMM(h_, tW2 + (size_t)it * DD * HDm, tb2 + (size_t)it * DD, f_, NTOK, DD, HDm, 0);
        ln_kernel<<<(NTOK + 7) / 8, 256>>>(f_, y1_, tln2g + it * DD, tln2b + it * DD, a_);
        add_mem_kernel<<<(NTOK * DD + 255) / 256, 256>>>();
    }

    // out = leakyrelu(y @ W_out^T)
    GEMM(y_, W_out, nullptr, out, NTOK, 64, DD, 2);
}

// round 4
// speedup vs baseline: 1.0573x; 1.0573x over previous
#include <cuda_runtime.h>
#include <math.h>
#include <stdint.h>

// Problem constants
#define BB   16
#define CC   32
#define TT   62
#define VV   19
#define DD   128
#define HH   8
#define HDm  256          // hidden dim of FFN / emb
#define NBT  (BB*TT)      // 992
#define NTOK (NBT*VV)     // 18848
#define NPAIR (VV*VV)     // 361

// ---------------- scratch buffers (device globals; no allocation allowed) ----------------
__device__ float d_p   [NTOK*CC];     // p  [bt, v, c]
__device__ float d_y   [NTOK*DD];     // running activation (flat [tokens,128])
__device__ float d_e   [NTOK*HDm];    // e = p @ W_emb^T
__device__ float d_bias[NBT*NPAIR*HH];// attn bias [bt, i, j, h]
__device__ float d_qkv [NTOK*384];
__device__ float d_a   [NTOK*DD];
__device__ float d_y1  [NTOK*DD];
__device__ float d_h   [NTOK*HDm];
__device__ float d_f   [NTOK*DD];
__device__ float d_mem [NTOK*DD];
__device__ float d_pe  [TT*DD];

// ---------------- p builder: pose [B,C,T,V] -> p [B,T,V,C] ----------------
__global__ void build_p_kernel(const float* __restrict__ pose) {
    int idx = blockIdx.x * 256 + threadIdx.x;
    if (idx >= NTOK * CC) return;
    int c  = idx & 31;
    int v  = (idx >> 5) % VV;
    int bt = idx / (CC * VV);
    int b = bt / TT, t = bt % TT;
    d_p[idx] = pose[(((size_t)b * CC + c) * TT + t) * VV + v];
}

// ---------------- positional encoding ----------------
__global__ void build_pe_kernel() {
    int t = blockIdx.x, c = threadIdx.x;
    int i2 = c & ~1;
    float div = expf((float)i2 * (-9.210340371976184f / 128.f)); // -ln(10000)/128
    float ang = (float)t * div;
    d_pe[t * DD + c] = (c & 1) ? cosf(ang) : sinf(ang);
}

// ---------------- 128x128x16 double-buffered SGEMM: C = act(A[M,K] @ W[N,K]^T + bias) ----
// act: 0 = none, 1 = relu, 2 = leakyrelu(0.01)
// act: 3 = "pe epilogue": v += pe[row%62][col]; write C (=y) and C2 (=mem)
#define BM 128
#define BN 128
#define BKg 16
#define APAD 132   // pad so transposed STS is (mostly) conflict-free; 132%4==0 keeps f4 align

__global__ __launch_bounds__(256)
void gemm128_kernel(const float* __restrict__ A, const float* __restrict__ W,
                    const float* __restrict__ bias, float* __restrict__ C,
                    float* __restrict__ C2,
                    int M, int N, int K, int act)
{
    __shared__ float As[2][BKg][APAD];
    __shared__ float Bs[2][BKg][APAD];
    int tid = threadIdx.x;
    int m0 = blockIdx.x * BM;
    int n0 = blockIdx.y * BN;
    int tm = (tid >> 4) * 8;
    int tn = (tid & 15) * 8;

    // loader mapping: 512 float4 per operand tile; this thread handles q = tid and tid+256
    int row0 = tid >> 2,        kq0 = (tid & 3) * 4;
    int row1 = (tid + 256) >> 2, kq1 = ((tid + 256) & 3) * 4;

    float4 pa0, pa1, pb0, pb1;
    float acc[8][8] = {};

    const int nk = K / BKg;

    // prefetch tile 0
    {
        int k0 = 0;
        pa0 = (m0 + row0 < M) ? *(const float4*)(A + (size_t)(m0 + row0) * K + k0 + kq0)
                              : make_float4(0.f, 0.f, 0.f, 0.f);
        pa1 = (m0 + row1 < M) ? *(const float4*)(A + (size_t)(m0 + row1) * K + k0 + kq1)
                              : make_float4(0.f, 0.f, 0.f, 0.f);
        pb0 = (n0 + row0 < N) ? *(const float4*)(W + (size_t)(n0 + row0) * K + k0 + kq0)
                              : make_float4(0.f, 0.f, 0.f, 0.f);
        pb1 = (n0 + row1 < N) ? *(const float4*)(W + (size_t)(n0 + row1) * K + k0 + kq1)
                              : make_float4(0.f, 0.f, 0.f, 0.f);
        As[0][kq0+0][row0] = pa0.x; As[0][kq0+1][row0] = pa0.y;
        As[0][kq0+2][row0] = pa0.z; As[0][kq0+3][row0] = pa0.w;
        As[0][kq1+0][row1] = pa1.x; As[0][kq1+1][row1] = pa1.y;
        As[0][kq1+2][row1] = pa1.z; As[0][kq1+3][row1] = pa1.w;
        Bs[0][kq0+0][row0] = pb0.x; Bs[0][kq0+1][row0] = pb0.y;
        Bs[0][kq0+2][row0] = pb0.z; Bs[0][kq0+3][row0] = pb0.w;
        Bs[0][kq1+0][row1] = pb1.x; Bs[0][kq1+1][row1] = pb1.y;
        Bs[0][kq1+2][row1] = pb1.z; Bs[0][kq1+3][row1] = pb1.w;
    }
    __syncthreads();

    for (int kt = 0; kt < nk; kt++) {
        int cur = kt & 1;
        if (kt + 1 < nk) {
            int k0 = (kt + 1) * BKg;
            pa0 = (m0 + row0 < M) ? *(const float4*)(A + (size_t)(m0 + row0) * K + k0 + kq0)
                                  : make_float4(0.f, 0.f, 0.f, 0.f);
            pa1 = (m0 + row1 < M) ? *(const float4*)(A + (size_t)(m0 + row1) * K + k0 + kq1)
                                  : make_float4(0.f, 0.f, 0.f, 0.f);
            pb0 = (n0 + row0 < N) ? *(const float4*)(W + (size_t)(n0 + row0) * K + k0 + kq0)
                                  : make_float4(0.f, 0.f, 0.f, 0.f);
            pb1 = (n0 + row1 < N) ? *(const float4*)(W + (size_t)(n0 + row1) * K + k0 + kq1)
                                  : make_float4(0.f, 0.f, 0.f, 0.f);
        }
        #pragma unroll
        for (int k = 0; k < BKg; k++) {
            float4 a0 = *(const float4*)&As[cur][k][tm];
            float4 a1 = *(const float4*)&As[cur][k][tm + 4];
            float4 b0 = *(const float4*)&Bs[cur][k][tn];
            float4 b1 = *(const float4*)&Bs[cur][k][tn + 4];
            float am[8] = {a0.x, a0.y, a0.z, a0.w, a1.x, a1.y, a1.z, a1.w};
            float bn[8] = {b0.x, b0.y, b0.z, b0.w, b1.x, b1.y, b1.z, b1.w};
            #pragma unroll
            for (int i = 0; i < 8; i++)
                #pragma unroll
                for (int j = 0; j < 8; j++) acc[i][j] += am[i] * bn[j];
        }
        if (kt + 1 < nk) {
            int nb = cur ^ 1;
            As[nb][kq0+0][row0] = pa0.x; As[nb][kq0+1][row0] = pa0.y;
            As[nb][kq0+2][row0] = pa0.z; As[nb][kq0+3][row0] = pa0.w;
            As[nb][kq1+0][row1] = pa1.x; As[nb][kq1+1][row1] = pa1.y;
            As[nb][kq1+2][row1] = pa1.z; As[nb][kq1+3][row1] = pa1.w;
            Bs[nb][kq0+0][row0] = pb0.x; Bs[nb][kq0+1][row0] = pb0.y;
            Bs[nb][kq0+2][row0] = pb0.z; Bs[nb][kq0+3][row0] = pb0.w;
            Bs[nb][kq1+0][row1] = pb1.x; Bs[nb][kq1+1][row1] = pb1.y;
            Bs[nb][kq1+2][row1] = pb1.z; Bs[nb][kq1+3][row1] = pb1.w;
            __syncthreads();
        }
    }

    // epilogue
    bool fullN = (n0 + BN <= N);
    #pragma unroll
    for (int i = 0; i < 8; i++) {
        int row = m0 + tm + i;
        if (row >= M) continue;
        float bvals[8];
        #pragma unroll
        for (int j = 0; j < 8; j++) {
            int col = n0 + tn + j;
            float v = acc[i][j];
            if (bias && (fullN || col < N)) v += bias[col];
            if (act == 1) v = fmaxf(v, 0.f);
            else if (act == 2) v = (v >= 0.f) ? v : 0.01f * v;
            else if (act == 3) v += d_pe[(row % TT) * DD + ((n0 + tn + j) & 127)];
            bvals[j] = v;
        }
        if (fullN) {
            float* cp = C + (size_t)row * N + n0 + tn;
            *(float4*)(cp)     = make_float4(bvals[0], bvals[1], bvals[2], bvals[3]);
            *(float4*)(cp + 4) = make_float4(bvals[4], bvals[5], bvals[6], bvals[7]);
            if (act == 3) {
                float* c2 = C2 + (size_t)row * N + n0 + tn;
                *(float4*)(c2)     = make_float4(bvals[0], bvals[1], bvals[2], bvals[3]);
                *(float4*)(c2 + 4) = make_float4(bvals[4], bvals[5], bvals[6], bvals[7]);
            }
        } else {
            #pragma unroll
            for (int j = 0; j < 8; j++) {
                int col = n0 + tn + j;
                if (col < N) {
                    C[(size_t)row * N + col] = bvals[j];
                    if (act == 3) C2[(size_t)row * N + col] = bvals[j];
                }
            }
        }
    }
}

// ---------------- fused pairwise bias: bias[bt,i,j,g] = (1/sqrt(8)) * sum_k Wb[g,k]*prelu(e_j[k]-e_i[k]) ----
__global__ __launch_bounds__(256)
void bias_kernel(const float* __restrict__ E, const float* __restrict__ WB,
                 const float* __restrict__ prelu_a, int iter, float* __restrict__ OUT)
{
    __shared__ float es[VV * HDm];   // 19*256
    __shared__ float wb[HH * HDm];   // 8*256
    int bt = blockIdx.x;
    int tid = threadIdx.x;
    for (int idx = tid; idx < VV * HDm; idx += 256)
        es[idx] = E[((size_t)bt * VV) * HDm + idx];
    for (int idx = tid; idx < HH * HDm; idx += 256)
        wb[idx] = WB[idx];
    float aP = prelu_a[iter];
    __syncthreads();

    int warp = tid >> 5, lane = tid & 31;
    for (int pr = warp; pr < NPAIR; pr += 8) {
        int vi = pr / VV, vj = pr % VV;
        float acc[8] = {0,0,0,0,0,0,0,0};
        #pragma unroll
        for (int u = 0; u < 8; u++) {
            int k = u * 32 + lane;
            float hv = es[vj * HDm + k] - es[vi * HDm + k];
            hv = (hv >= 0.f) ? hv : aP * hv;
            #pragma unroll
            for (int g = 0; g < 8; g++) acc[g] += hv * wb[g * HDm + k];
        }
        #pragma unroll
        for (int g = 0; g < 8; g++)
            #pragma unroll
            for (int o = 16; o; o >>= 1)
                acc[g] += __shfl_xor_sync(0xffffffffu, acc[g], o);
        if (lane == 0) {
            float* o = OUT + (((size_t)bt * VV + vi) * VV + vj) * HH;
            #pragma unroll
            for (int g = 0; g < 8; g++) o[g] = acc[g] * 0.3535533906f;
        }
    }
}

// ---------------- graph attention (N=19, per-head bias) ----------------
__global__ __launch_bounds__(256)
void graph_attn_kernel(const float* __restrict__ QKV, const float* __restrict__ BIAS,
                       float* __restrict__ OUT)
{
    __shared__ float qs[VV * DD];      // [n][c]
    __shared__ float ks[DD * VV];      // [c][j]  stride 19 (conflict-free)
    __shared__ float vs[DD * VV];
    int bt = blockIdx.x;
    int tid = threadIdx.x;
    for (int idx = tid; idx < VV * DD; idx += 256) {
        int n = idx >> 7, c = idx & 127;
        const float* row = QKV + (size_t)(bt * VV + n) * 384;
        qs[idx] = row[c];
        ks[c * VV + n] = row[128 + c];
        vs[c * VV + n] = row[256 + c];
    }
    __syncthreads();
    int h = tid >> 5, lane = tid & 31;
    for (int i = 0; i < VV; i++) {
        float sc = -1e30f;
        if (lane < VV) {
            float acc = 0.f;
            #pragma unroll
            for (int c = 0; c < 16; c++)
                acc += qs[i * DD + h * 16 + c] * ks[(h * 16 + c) * VV + lane];
            sc = acc * 0.25f + BIAS[(((size_t)bt * VV + i) * VV + lane) * HH + h];
        }
        float mx = sc;
        #pragma unroll
        for (int o = 16; o; o >>= 1) mx = fmaxf(mx, __shfl_xor_sync(0xffffffffu, mx, o));
        float ev = (lane < VV) ? __expf(sc - mx) : 0.f;
        float sum = ev;
        #pragma unroll
        for (int o = 16; o; o >>= 1) sum += __shfl_xor_sync(0xffffffffu, sum, o);
        float aj = ev / sum;
        float o_acc = 0.f;
        int cc = lane & 15;
        #pragma unroll
        for (int j = 0; j < VV; j++) {
            float aw = __shfl_sync(0xffffffffu, aj, j);
            o_acc += aw * vs[(h * 16 + cc) * VV + j];
        }
        if (lane < 16) OUT[(size_t)(bt * VV + i) * DD + h * 16 + lane] = o_acc;
    }
}

// ---------------- temporal attention (N=62, no bias) ----------------
__global__ __launch_bounds__(128)
void temporal_attn_kernel(const float* __restrict__ QKV, float* __restrict__ OUT)
{
    __shared__ float ks[16 * 65];
    __shared__ float vs[16 * 65];
    int bn = blockIdx.x, h = blockIdx.y;
    int tid = threadIdx.x;
    for (int idx = tid; idx < 16 * 64; idx += 128) {
        int c = idx >> 6, n = idx & 63;
        float kv = 0.f, vv = 0.f;
        if (n < TT) {
            const float* row = QKV + (size_t)(bn * TT + n) * 384 + h * 16 + c;
            kv = row[128];
            vv = row[256];
        }
        ks[c * 65 + n] = kv;
        vs[c * 65 + n] = vv;
    }
    __syncthreads();
    int warp = tid >> 5, lane = tid & 31;
    for (int i = warp; i < TT; i += 4) {
        float q = (lane < 16) ? QKV[(size_t)(bn * TT + i) * 384 + h * 16 + lane] : 0.f;
        float s0 = 0.f, s1 = 0.f;
        #pragma unroll
        for (int c = 0; c < 16; c++) {
            float qc = __shfl_sync(0xffffffffu, q, c);
            s0 += qc * ks[c * 65 + lane];
            s1 += qc * ks[c * 65 + lane + 32];
        }
        s0 *= 0.25f; s1 *= 0.25f;
        bool v1 = (lane + 32) < TT;
        float mx = fmaxf(s0, v1 ? s1 : -1e30f);
        #pragma unroll
        for (int o = 16; o; o >>= 1) mx = fmaxf(mx, __shfl_xor_sync(0xffffffffu, mx, o));
        float e0 = __expf(s0 - mx);
        float e1 = v1 ? __expf(s1 - mx) : 0.f;
        float sum = e0 + e1;
        #pragma unroll
        for (int o = 16; o; o >>= 1) sum += __shfl_xor_sync(0xffffffffu, sum, o);
        float inv = 1.f / sum;
        e0 *= inv; e1 *= inv;
        float o_acc = 0.f;
        int cc = lane & 15;
        #pragma unroll
        for (int j = 0; j < 32; j++) {
            float aw = __shfl_sync(0xffffffffu, e0, j);
            o_acc += aw * vs[cc * 65 + j];
        }
        #pragma unroll
        for (int j = 32; j < TT; j++) {
            float aw = __shfl_sync(0xffffffffu, e1, j - 32);
            o_acc += aw * vs[cc * 65 + j];
        }
        if (lane < 16) OUT[(size_t)(bn * TT + i) * DD + h * 16 + lane] = o_acc;
    }
}

// ---------------- LayerNorm: out = LN(X + R) * g + b (+ ADD)  (D=128, one warp/row) ----------------
__global__ __launch_bounds__(256)
void ln_kernel(const float* __restrict__ X, const float* __restrict__ R,
               const float* __restrict__ g, const float* __restrict__ b,
               float* __restrict__ OUT, const float* __restrict__ ADD)
{
    int warp = threadIdx.x >> 5, lane = threadIdx.x & 31;
    int row = blockIdx.x * 8 + warp;
    if (row >= NTOK) return;
    const float* x = X + (size_t)row * DD;
    const float* r = R + (size_t)row * DD;
    float v[4];
    #pragma unroll
    for (int u = 0; u < 4; u++) v[u] = x[lane + u * 32] + r[lane + u * 32];
    float s = v[0] + v[1] + v[2] + v[3];
    #pragma unroll
    for (int o = 16; o; o >>= 1) s += __shfl_xor_sync(0xffffffffu, s, o);
    float m = s * (1.f / 128.f);
    float sv = 0.f;
    #pragma unroll
    for (int u = 0; u < 4; u++) { float dlt = v[u] - m; sv += dlt * dlt; }
    #pragma unroll
    for (int o = 16; o; o >>= 1) sv += __shfl_xor_sync(0xffffffffu, sv, o);
    float rinv = rsqrtf(sv * (1.f / 128.f) + 1e-5f);
    #pragma unroll
    for (int u = 0; u < 4; u++) {
        int c = lane + u * 32;
        float o = (v[u] - m) * rinv * g[c] + b[c];
        if (ADD) o += ADD[(size_t)row * DD + c];
        OUT[(size_t)row * DD + c] = o;
    }
}

// ---------------- host launcher ----------------
static void GEMM(const float* A, const float* W, const float* bias, float* C,
                 int M, int N, int K, int act, float* C2 = nullptr)
{
    dim3 grid((M + BM - 1) / BM, (N + BN - 1) / BN);
    gemm128_kernel<<<grid, 256>>>(A, W, bias, C, C2, M, N, K, act);
}

extern "C" void kernel_launch(void* const* d_in, const int* in_sizes, int n_in,
                              void* d_out, int out_size)
{
    const float* pose    = (const float*)d_in[0];
    const float* W_pose  = (const float*)d_in[1];
    const float* W_emb   = (const float*)d_in[2];
    const float* prelu_a = (const float*)d_in[3];
    const float* W_bias  = (const float*)d_in[4];
    const float* gWqkv   = (const float*)d_in[5];
    const float* gbqkv   = (const float*)d_in[6];
    const float* gWo     = (const float*)d_in[7];
    const float* gbo     = (const float*)d_in[8];
    const float* gln1g   = (const float*)d_in[9];
    const float* gln1b   = (const float*)d_in[10];
    const float* gW1     = (const float*)d_in[11];
    const float* gb1     = (const float*)d_in[12];
    const float* gW2     = (const float*)d_in[13];
    const float* gb2     = (const float*)d_in[14];
    const float* gln2g   = (const float*)d_in[15];
    const float* gln2b   = (const float*)d_in[16];
    const float* deW     = (const float*)d_in[17];
    const float* deb     = (const float*)d_in[18];
    const float* tWqkv   = (const float*)d_in[19];
    const float* tbqkv   = (const float*)d_in[20];
    const float* tWo     = (const float*)d_in[21];
    const float* tbo     = (const float*)d_in[22];
    const float* tln1g   = (const float*)d_in[23];
    const float* tln1b   = (const float*)d_in[24];
    const float* tW1     = (const float*)d_in[25];
    const float* tb1     = (const float*)d_in[26];
    const float* tW2     = (const float*)d_in[27];
    const float* tb2     = (const float*)d_in[28];
    const float* tln2g   = (const float*)d_in[29];
    const float* tln2b   = (const float*)d_in[30];
    const float* W_out   = (const float*)d_in[31];
    float* out = (float*)d_out;

    float *p_, *y_, *e_, *bias_, *qkv_, *a_, *y1_, *h_, *f_, *mem_;
    cudaGetSymbolAddress((void**)&p_,    d_p);
    cudaGetSymbolAddress((void**)&y_,    d_y);
    cudaGetSymbolAddress((void**)&e_,    d_e);
    cudaGetSymbolAddress((void**)&bias_, d_bias);
    cudaGetSymbolAddress((void**)&qkv_,  d_qkv);
    cudaGetSymbolAddress((void**)&a_,    d_a);
    cudaGetSymbolAddress((void**)&y1_,   d_y1);
    cudaGetSymbolAddress((void**)&h_,    d_h);
    cudaGetSymbolAddress((void**)&f_,    d_f);
    cudaGetSymbolAddress((void**)&mem_,  d_mem);

    build_p_kernel<<<(NTOK * CC + 255) / 256, 256>>>(pose);
    build_pe_kernel<<<TT, DD>>>();
    // y0 = p @ W_pose^T
    GEMM(p_, W_pose, nullptr, y_, NTOK, DD, CC, 0);

    for (int it = 0; it < 2; it++) {
        // ---- pairwise bias (linear-in-diff trick) ----
        GEMM(p_, W_emb + (size_t)it * HDm * CC, nullptr, e_, NTOK, HDm, CC, 0);
        bias_kernel<<<NBT, 256>>>(e_, W_bias + (size_t)it * HH * HDm, prelu_a, it, bias_);

        // ---- graph encoder block (rows = bt*19+v) ----
        GEMM(y_, gWqkv + (size_t)it * 3 * DD * DD, gbqkv + (size_t)it * 3 * DD,
             qkv_, NTOK, 384, DD, 0);
        graph_attn_kernel<<<NBT, 256>>>(qkv_, bias_, a_);
        GEMM(a_, gWo + (size_t)it * DD * DD, gbo + (size_t)it * DD, f_, NTOK, DD, DD, 0);
        ln_kernel<<<(NTOK + 7) / 8, 256>>>(f_, y_, gln1g + it * DD, gln1b + it * DD, y1_, nullptr);
        GEMM(y1_, gW1 + (size_t)it * HDm * DD, gb1 + (size_t)it * HDm, h_, NTOK, HDm, DD, 1);
        GEMM(h_, gW2 + (size_t)it * DD * HDm, gb2 + (size_t)it * DD, f_, NTOK, DD, HDm, 0);
        ln_kernel<<<(NTOK + 7) / 8, 256>>>(f_, y1_, gln2g + it * DD, gln2b + it * DD, a_, nullptr);
        // de linear, fused with positional-encoding add; writes y and mem
        // (reinterpret [B,T,V,D] flat -> [B*V, T, D] is a no-op on flat memory)
        GEMM(a_, deW + (size_t)it * DD * DD, deb + (size_t)it * DD, y_, NTOK, DD, DD, 3, mem_);

        // ---- temporal encoder block (rows = m*62+t, same flat buffer) ----
        GEMM(y_, tWqkv + (size_t)it * 3 * DD * DD, tbqkv + (size_t)it * 3 * DD,
             qkv_, NTOK, 384, DD, 0);
        {
            dim3 grid(BB * VV, HH);
            temporal_attn_kernel<<<grid, 128>>>(qkv_, a_);
        }
        GEMM(a_, tWo + (size_t)it * DD * DD, tbo + (size_t)it * DD, f_, NTOK, DD, DD, 0);
        ln_kernel<<<(NTOK + 7) / 8, 256>>>(f_, y_, tln1g + it * DD, tln1b + it * DD, y1_, nullptr);
        GEMM(y1_, tW1 + (size_t)it * HDm * DD, tb1 + (size_t)it * HDm, h_, NTOK, HDm, DD, 1);
        GEMM(h_, tW2 + (size_t)it * DD * HDm, tb2 + (size_t)it * DD, f_, NTOK, DD, HDm, 0);
        // ln2 with fused "+ mem" epilogue writes y directly
        ln_kernel<<<(NTOK + 7) / 8, 256>>>(f_, y1_, tln2g + it * DD, tln2b + it * DD, y_, mem_);
    }

    // out = leakyrelu(y @ W_out^T)
    GEMM(y_, W_out, nullptr, out, NTOK, 64, DD, 2);
}

// round 5
// speedup vs baseline: 1.0623x; 1.0046x over previous
#include <cuda_runtime.h>
#include <math.h>
#include <stdint.h>

// Problem constants
#define BB   16
#define CC   32
#define TT   62
#define VV   19
#define DD   128
#define HH   8
#define HDm  256          // hidden dim of FFN / emb
#define NBT  (BB*TT)      // 992
#define NTOK (NBT*VV)     // 18848
#define NPAIR (VV*VV)     // 361

// ---------------- scratch buffers (device globals; no allocation allowed) ----------------
__device__ float d_p   [NTOK*CC];     // p  [bt, v, c]
__device__ float d_y   [NTOK*DD];     // running activation (flat [tokens,128])
__device__ float d_e   [NTOK*HDm];    // e = p @ W_emb^T
__device__ float d_bias[NBT*NPAIR*HH];// attn bias [bt, i, j, h]
__device__ float d_qkv [NTOK*384];
__device__ float d_a   [NTOK*DD];
__device__ float d_y1  [NTOK*DD];
__device__ float d_h   [NTOK*HDm];
__device__ float d_mem [NTOK*DD];
__device__ float d_pe  [TT*DD];

// ---------------- p builder: pose [B,C,T,V] -> p [B,T,V,C] ----------------
__global__ void build_p_kernel(const float* __restrict__ pose) {
    int idx = blockIdx.x * 256 + threadIdx.x;
    if (idx >= NTOK * CC) return;
    int c  = idx & 31;
    int v  = (idx >> 5) % VV;
    int bt = idx / (CC * VV);
    int b = bt / TT, t = bt % TT;
    d_p[idx] = pose[(((size_t)b * CC + c) * TT + t) * VV + v];
}

// ---------------- positional encoding ----------------
__global__ void build_pe_kernel() {
    int t = blockIdx.x, c = threadIdx.x;
    int i2 = c & ~1;
    float div = expf((float)i2 * (-9.210340371976184f / 128.f)); // -ln(10000)/128
    float ang = (float)t * div;
    d_pe[t * DD + c] = (c & 1) ? cosf(ang) : sinf(ang);
}

// ---------------- 128x128x16 double-buffered SGEMM ----------------
// C = act(A[M,K] @ W[N,K]^T + bias)
// act 0: none; 1: relu; 2: leakyrelu(0.01)
// act 3: += pe[row%62][col]; write C and C2          (requires N==128)
// act 4: C = LN(v + R[row]) * lng + lnb              (requires N==128, full rows per block)
// act 5: like 4, then += ADD[row]                    (requires N==128)
#define BM 128
#define BN 128
#define BKg 16
#define APAD 132

__global__ __launch_bounds__(256, 2)
void gemm128_kernel(const float* __restrict__ A, const float* __restrict__ W,
                    const float* __restrict__ bias, float* __restrict__ C,
                    float* __restrict__ C2,
                    const float* __restrict__ R, const float* __restrict__ lng,
                    const float* __restrict__ lnb, const float* __restrict__ ADD,
                    int M, int N, int K, int act)
{
    __shared__ float As[2][BKg][APAD];
    __shared__ float Bs[2][BKg][APAD];
    int tid = threadIdx.x;
    int m0 = blockIdx.x * BM;
    int n0 = blockIdx.y * BN;
    int tm = (tid >> 4) * 8;
    int tn = (tid & 15) * 8;

    int row0 = tid >> 2,         kq0 = (tid & 3) * 4;
    int row1 = (tid + 256) >> 2, kq1 = ((tid + 256) & 3) * 4;

    float4 pa0, pa1, pb0, pb1;
    float acc[8][8] = {};

    const int nk = K / BKg;

    {
        pa0 = (m0 + row0 < M) ? *(const float4*)(A + (size_t)(m0 + row0) * K + kq0)
                              : make_float4(0.f, 0.f, 0.f, 0.f);
        pa1 = (m0 + row1 < M) ? *(const float4*)(A + (size_t)(m0 + row1) * K + kq1)
                              : make_float4(0.f, 0.f, 0.f, 0.f);
        pb0 = (n0 + row0 < N) ? *(const float4*)(W + (size_t)(n0 + row0) * K + kq0)
                              : make_float4(0.f, 0.f, 0.f, 0.f);
        pb1 = (n0 + row1 < N) ? *(const float4*)(W + (size_t)(n0 + row1) * K + kq1)
                              : make_float4(0.f, 0.f, 0.f, 0.f);
        As[0][kq0+0][row0] = pa0.x; As[0][kq0+1][row0] = pa0.y;
        As[0][kq0+2][row0] = pa0.z; As[0][kq0+3][row0] = pa0.w;
        As[0][kq1+0][row1] = pa1.x; As[0][kq1+1][row1] = pa1.y;
        As[0][kq1+2][row1] = pa1.z; As[0][kq1+3][row1] = pa1.w;
        Bs[0][kq0+0][row0] = pb0.x; Bs[0][kq0+1][row0] = pb0.y;
        Bs[0][kq0+2][row0] = pb0.z; Bs[0][kq0+3][row0] = pb0.w;
        Bs[0][kq1+0][row1] = pb1.x; Bs[0][kq1+1][row1] = pb1.y;
        Bs[0][kq1+2][row1] = pb1.z; Bs[0][kq1+3][row1] = pb1.w;
    }
    __syncthreads();

    for (int kt = 0; kt < nk; kt++) {
        int cur = kt & 1;
        if (kt + 1 < nk) {
            int k0 = (kt + 1) * BKg;
            pa0 = (m0 + row0 < M) ? *(const float4*)(A + (size_t)(m0 + row0) * K + k0 + kq0)
                                  : make_float4(0.f, 0.f, 0.f, 0.f);
            pa1 = (m0 + row1 < M) ? *(const float4*)(A + (size_t)(m0 + row1) * K + k0 + kq1)
                                  : make_float4(0.f, 0.f, 0.f, 0.f);
            pb0 = (n0 + row0 < N) ? *(const float4*)(W + (size_t)(n0 + row0) * K + k0 + kq0)
                                  : make_float4(0.f, 0.f, 0.f, 0.f);
            pb1 = (n0 + row1 < N) ? *(const float4*)(W + (size_t)(n0 + row1) * K + k0 + kq1)
                                  : make_float4(0.f, 0.f, 0.f, 0.f);
        }
        #pragma unroll
        for (int k = 0; k < BKg; k++) {
            float4 a0 = *(const float4*)&As[cur][k][tm];
            float4 a1 = *(const float4*)&As[cur][k][tm + 4];
            float4 b0 = *(const float4*)&Bs[cur][k][tn];
            float4 b1 = *(const float4*)&Bs[cur][k][tn + 4];
            float am[8] = {a0.x, a0.y, a0.z, a0.w, a1.x, a1.y, a1.z, a1.w};
            float bn[8] = {b0.x, b0.y, b0.z, b0.w, b1.x, b1.y, b1.z, b1.w};
            #pragma unroll
            for (int i = 0; i < 8; i++)
                #pragma unroll
                for (int j = 0; j < 8; j++) acc[i][j] = fmaf(am[i], bn[j], acc[i][j]);
        }
        if (kt + 1 < nk) {
            int nb = cur ^ 1;
            As[nb][kq0+0][row0] = pa0.x; As[nb][kq0+1][row0] = pa0.y;
            As[nb][kq0+2][row0] = pa0.z; As[nb][kq0+3][row0] = pa0.w;
            As[nb][kq1+0][row1] = pa1.x; As[nb][kq1+1][row1] = pa1.y;
            As[nb][kq1+2][row1] = pa1.z; As[nb][kq1+3][row1] = pa1.w;
            Bs[nb][kq0+0][row0] = pb0.x; Bs[nb][kq0+1][row0] = pb0.y;
            Bs[nb][kq0+2][row0] = pb0.z; Bs[nb][kq0+3][row0] = pb0.w;
            Bs[nb][kq1+0][row1] = pb1.x; Bs[nb][kq1+1][row1] = pb1.y;
            Bs[nb][kq1+2][row1] = pb1.z; Bs[nb][kq1+3][row1] = pb1.w;
            __syncthreads();
        }
    }

    if (act >= 4) {
        // ---- fused LayerNorm epilogue (N == 128, full rows in this block) ----
        #pragma unroll
        for (int i = 0; i < 8; i++) {
            int row = m0 + tm + i;
            if (row >= M) continue;
            // v = gemm + bias + residual
            float v[8];
            float4 r0 = *(const float4*)(R + (size_t)row * DD + tn);
            float4 r1 = *(const float4*)(R + (size_t)row * DD + tn + 4);
            v[0] = acc[i][0] + bias[tn+0] + r0.x; v[1] = acc[i][1] + bias[tn+1] + r0.y;
            v[2] = acc[i][2] + bias[tn+2] + r0.z; v[3] = acc[i][3] + bias[tn+3] + r0.w;
            v[4] = acc[i][4] + bias[tn+4] + r1.x; v[5] = acc[i][5] + bias[tn+5] + r1.y;
            v[6] = acc[i][6] + bias[tn+6] + r1.z; v[7] = acc[i][7] + bias[tn+7] + r1.w;
            float s = v[0]+v[1]+v[2]+v[3]+v[4]+v[5]+v[6]+v[7];
            #pragma unroll
            for (int o = 1; o < 16; o <<= 1) s += __shfl_xor_sync(0xffffffffu, s, o);
            float m = s * (1.f / 128.f);
            float q = 0.f;
            #pragma unroll
            for (int j = 0; j < 8; j++) { float dlt = v[j] - m; q += dlt * dlt; }
            #pragma unroll
            for (int o = 1; o < 16; o <<= 1) q += __shfl_xor_sync(0xffffffffu, q, o);
            float rinv = rsqrtf(q * (1.f / 128.f) + 1e-5f);
            float outv[8];
            #pragma unroll
            for (int j = 0; j < 8; j++) {
                int col = tn + j;
                outv[j] = (v[j] - m) * rinv * lng[col] + lnb[col];
            }
            if (act == 5) {
                float4 d0 = *(const float4*)(ADD + (size_t)row * DD + tn);
                float4 d1 = *(const float4*)(ADD + (size_t)row * DD + tn + 4);
                outv[0]+=d0.x; outv[1]+=d0.y; outv[2]+=d0.z; outv[3]+=d0.w;
                outv[4]+=d1.x; outv[5]+=d1.y; outv[6]+=d1.z; outv[7]+=d1.w;
            }
            float* cp = C + (size_t)row * DD + tn;
            *(float4*)(cp)     = make_float4(outv[0], outv[1], outv[2], outv[3]);
            *(float4*)(cp + 4) = make_float4(outv[4], outv[5], outv[6], outv[7]);
        }
        return;
    }

    // ---- standard epilogue ----
    bool fullN = (n0 + BN <= N);
    #pragma unroll
    for (int i = 0; i < 8; i++) {
        int row = m0 + tm + i;
        if (row >= M) continue;
        float bvals[8];
        #pragma unroll
        for (int j = 0; j < 8; j++) {
            int col = n0 + tn + j;
            float v = acc[i][j];
            if (bias && (fullN || col < N)) v += bias[col];
            if (act == 1) v = fmaxf(v, 0.f);
            else if (act == 2) v = (v >= 0.f) ? v : 0.01f * v;
            else if (act == 3) v += d_pe[(row % TT) * DD + ((n0 + tn + j) & 127)];
            bvals[j] = v;
        }
        if (fullN) {
            float* cp = C + (size_t)row * N + n0 + tn;
            *(float4*)(cp)     = make_float4(bvals[0], bvals[1], bvals[2], bvals[3]);
            *(float4*)(cp + 4) = make_float4(bvals[4], bvals[5], bvals[6], bvals[7]);
            if (act == 3) {
                float* c2 = C2 + (size_t)row * N + n0 + tn;
                *(float4*)(c2)     = make_float4(bvals[0], bvals[1], bvals[2], bvals[3]);
                *(float4*)(c2 + 4) = make_float4(bvals[4], bvals[5], bvals[6], bvals[7]);
            }
        } else {
            #pragma unroll
            for (int j = 0; j < 8; j++) {
                int col = n0 + tn + j;
                if (col < N) {
                    C[(size_t)row * N + col] = bvals[j];
                    if (act == 3) C2[(size_t)row * N + col] = bvals[j];
                }
            }
        }
    }
}

// ---------------- fused pairwise bias ----------------
__global__ __launch_bounds__(256)
void bias_kernel(const float* __restrict__ E, const float* __restrict__ WB,
                 const float* __restrict__ prelu_a, int iter, float* __restrict__ OUT)
{
    __shared__ float es[VV * HDm];   // 19*256
    __shared__ float wb[HH * HDm];   // 8*256
    int bt = blockIdx.x;
    int tid = threadIdx.x;
    for (int idx = tid; idx < VV * HDm; idx += 256)
        es[idx] = E[((size_t)bt * VV) * HDm + idx];
    for (int idx = tid; idx < HH * HDm; idx += 256)
        wb[idx] = WB[idx];
    float aP = prelu_a[iter];
    __syncthreads();

    int warp = tid >> 5, lane = tid & 31;
    for (int pr = warp; pr < NPAIR; pr += 8) {
        int vi = pr / VV, vj = pr % VV;
        float acc[8] = {0,0,0,0,0,0,0,0};
        #pragma unroll
        for (int u = 0; u < 8; u++) {
            int k = u * 32 + lane;
            float hv = es[vj * HDm + k] - es[vi * HDm + k];
            hv = (hv >= 0.f) ? hv : aP * hv;
            #pragma unroll
            for (int g = 0; g < 8; g++) acc[g] += hv * wb[g * HDm + k];
        }
        #pragma unroll
        for (int g = 0; g < 8; g++)
            #pragma unroll
            for (int o = 16; o; o >>= 1)
                acc[g] += __shfl_xor_sync(0xffffffffu, acc[g], o);
        if (lane == 0) {
            float* o = OUT + (((size_t)bt * VV + vi) * VV + vj) * HH;
            #pragma unroll
            for (int g = 0; g < 8; g++) o[g] = acc[g] * 0.3535533906f;
        }
    }
}

// ---------------- graph attention (N=19, per-head bias) ----------------
__global__ __launch_bounds__(256)
void graph_attn_kernel(const float* __restrict__ QKV, const float* __restrict__ BIAS,
                       float* __restrict__ OUT)
{
    __shared__ float qs[VV * DD];      // [n][c]
    __shared__ float ks[DD * VV];      // [c][j]
    __shared__ float vs[DD * VV];
    int bt = blockIdx.x;
    int tid = threadIdx.x;
    for (int idx = tid; idx < VV * DD; idx += 256) {
        int n = idx >> 7, c = idx & 127;
        const float* row = QKV + (size_t)(bt * VV + n) * 384;
        qs[idx] = row[c];
        ks[c * VV + n] = row[128 + c];
        vs[c * VV + n] = row[256 + c];
    }
    __syncthreads();
    int h = tid >> 5, lane = tid & 31;
    for (int i = 0; i < VV; i++) {
        float sc = -1e30f;
        if (lane < VV) {
            float acc = 0.f;
            #pragma unroll
            for (int c = 0; c < 16; c++)
                acc += qs[i * DD + h * 16 + c] * ks[(h * 16 + c) * VV + lane];
            sc = acc * 0.25f + BIAS[(((size_t)bt * VV + i) * VV + lane) * HH + h];
        }
        float mx = sc;
        #pragma unroll
        for (int o = 16; o; o >>= 1) mx = fmaxf(mx, __shfl_xor_sync(0xffffffffu, mx, o));
        float ev = (lane < VV) ? __expf(sc - mx) : 0.f;
        float sum = ev;
        #pragma unroll
        for (int o = 16; o; o >>= 1) sum += __shfl_xor_sync(0xffffffffu, sum, o);
        float aj = ev / sum;
        float o_acc = 0.f;
        int cc = lane & 15;
        #pragma unroll
        for (int j = 0; j < VV; j++) {
            float aw = __shfl_sync(0xffffffffu, aj, j);
            o_acc += aw * vs[(h * 16 + cc) * VV + j];
        }
        if (lane < 16) OUT[(size_t)(bt * VV + i) * DD + h * 16 + lane] = o_acc;
    }
}

// ---------------- temporal attention (N=62, no bias) ----------------
__global__ __launch_bounds__(128)
void temporal_attn_kernel(const float* __restrict__ QKV, float* __restrict__ OUT)
{
    __shared__ float ks[16 * 65];
    __shared__ float vs[16 * 65];
    int bn = blockIdx.x, h = blockIdx.y;
    int tid = threadIdx.x;
    for (int idx = tid; idx < 16 * 64; idx += 128) {
        int c = idx >> 6, n = idx & 63;
        float kv = 0.f, vv = 0.f;
        if (n < TT) {
            const float* row = QKV + (size_t)(bn * TT + n) * 384 + h * 16 + c;
            kv = row[128];
            vv = row[256];
        }
        ks[c * 65 + n] = kv;
        vs[c * 65 + n] = vv;
    }
    __syncthreads();
    int warp = tid >> 5, lane = tid & 31;
    for (int i = warp; i < TT; i += 4) {
        float q = (lane < 16) ? QKV[(size_t)(bn * TT + i) * 384 + h * 16 + lane] : 0.f;
        float s0 = 0.f, s1 = 0.f;
        #pragma unroll
        for (int c = 0; c < 16; c++) {
            float qc = __shfl_sync(0xffffffffu, q, c);
            s0 += qc * ks[c * 65 + lane];
            s1 += qc * ks[c * 65 + lane + 32];
        }
        s0 *= 0.25f; s1 *= 0.25f;
        bool v1 = (lane + 32) < TT;
        float mx = fmaxf(s0, v1 ? s1 : -1e30f);
        #pragma unroll
        for (int o = 16; o; o >>= 1) mx = fmaxf(mx, __shfl_xor_sync(0xffffffffu, mx, o));
        float e0 = __expf(s0 - mx);
        float e1 = v1 ? __expf(s1 - mx) : 0.f;
        float sum = e0 + e1;
        #pragma unroll
        for (int o = 16; o; o >>= 1) sum += __shfl_xor_sync(0xffffffffu, sum, o);
        float inv = 1.f / sum;
        e0 *= inv; e1 *= inv;
        float o_acc = 0.f;
        int cc = lane & 15;
        #pragma unroll
        for (int j = 0; j < 32; j++) {
            float aw = __shfl_sync(0xffffffffu, e0, j);
            o_acc += aw * vs[cc * 65 + j];
        }
        #pragma unroll
        for (int j = 32; j < TT; j++) {
            float aw = __shfl_sync(0xffffffffu, e1, j - 32);
            o_acc += aw * vs[cc * 65 + j];
        }
        if (lane < 16) OUT[(size_t)(bn * TT + i) * DD + h * 16 + lane] = o_acc;
    }
}

// ---------------- host launcher ----------------
static void GEMM(const float* A, const float* W, const float* bias, float* C,
                 int M, int N, int K, int act, float* C2 = nullptr,
                 const float* R = nullptr, const float* lng = nullptr,
                 const float* lnb = nullptr, const float* ADD = nullptr)
{
    dim3 grid((M + BM - 1) / BM, (N + BN - 1) / BN);
    gemm128_kernel<<<grid, 256>>>(A, W, bias, C, C2, R, lng, lnb, ADD, M, N, K, act);
}

extern "C" void kernel_launch(void* const* d_in, const int* in_sizes, int n_in,
                              void* d_out, int out_size)
{
    const float* pose    = (const float*)d_in[0];
    const float* W_pose  = (const float*)d_in[1];
    const float* W_emb   = (const float*)d_in[2];
    const float* prelu_a = (const float*)d_in[3];
    const float* W_bias  = (const float*)d_in[4];
    const float* gWqkv   = (const float*)d_in[5];
    const float* gbqkv   = (const float*)d_in[6];
    const float* gWo     = (const float*)d_in[7];
    const float* gbo     = (const float*)d_in[8];
    const float* gln1g   = (const float*)d_in[9];
    const float* gln1b   = (const float*)d_in[10];
    const float* gW1     = (const float*)d_in[11];
    const float* gb1     = (const float*)d_in[12];
    const float* gW2     = (const float*)d_in[13];
    const float* gb2     = (const float*)d_in[14];
    const float* gln2g   = (const float*)d_in[15];
    const float* gln2b   = (const float*)d_in[16];
    const float* deW     = (const float*)d_in[17];
    const float* deb     = (const float*)d_in[18];
    const float* tWqkv   = (const float*)d_in[19];
    const float* tbqkv   = (const float*)d_in[20];
    const float* tWo     = (const float*)d_in[21];
    const float* tbo     = (const float*)d_in[22];
    const float* tln1g   = (const float*)d_in[23];
    const float* tln1b   = (const float*)d_in[24];
    const float* tW1     = (const float*)d_in[25];
    const float* tb1     = (const float*)d_in[26];
    const float* tW2     = (const float*)d_in[27];
    const float* tb2     = (const float*)d_in[28];
    const float* tln2g   = (const float*)d_in[29];
    const float* tln2b   = (const float*)d_in[30];
    const float* W_out   = (const float*)d_in[31];
    float* out = (float*)d_out;

    float *p_, *y_, *e_, *bias_, *qkv_, *a_, *y1_, *h_, *mem_;
    cudaGetSymbolAddress((void**)&p_,    d_p);
    cudaGetSymbolAddress((void**)&y_,    d_y);
    cudaGetSymbolAddress((void**)&e_,    d_e);
    cudaGetSymbolAddress((void**)&bias_, d_bias);
    cudaGetSymbolAddress((void**)&qkv_,  d_qkv);
    cudaGetSymbolAddress((void**)&a_,    d_a);
    cudaGetSymbolAddress((void**)&y1_,   d_y1);
    cudaGetSymbolAddress((void**)&h_,    d_h);
    cudaGetSymbolAddress((void**)&mem_,  d_mem);

    build_p_kernel<<<(NTOK * CC + 255) / 256, 256>>>(pose);
    build_pe_kernel<<<TT, DD>>>();
    // y0 = p @ W_pose^T
    GEMM(p_, W_pose, nullptr, y_, NTOK, DD, CC, 0);

    for (int it = 0; it < 2; it++) {
        // ---- pairwise bias (linear-in-diff trick) ----
        GEMM(p_, W_emb + (size_t)it * HDm * CC, nullptr, e_, NTOK, HDm, CC, 0);
        bias_kernel<<<NBT, 256>>>(e_, W_bias + (size_t)it * HH * HDm, prelu_a, it, bias_);

        // ---- graph encoder block (rows = bt*19+v) ----
        GEMM(y_, gWqkv + (size_t)it * 3 * DD * DD, gbqkv + (size_t)it * 3 * DD,
             qkv_, NTOK, 384, DD, 0);
        graph_attn_kernel<<<NBT, 256>>>(qkv_, bias_, a_);
        // Wo + residual(y) + LN1 -> y1  (fused)
        GEMM(a_, gWo + (size_t)it * DD * DD, gbo + (size_t)it * DD, y1_, NTOK, DD, DD, 4,
             nullptr, y_, gln1g + it * DD, gln1b + it * DD);
        GEMM(y1_, gW1 + (size_t)it * HDm * DD, gb1 + (size_t)it * HDm, h_, NTOK, HDm, DD, 1);
        // W2 + residual(y1) + LN2 -> a  (fused)
        GEMM(h_, gW2 + (size_t)it * DD * HDm, gb2 + (size_t)it * DD, a_, NTOK, DD, HDm, 4,
             nullptr, y1_, gln2g + it * DD, gln2b + it * DD);
        // de linear + pe -> y and mem
        GEMM(a_, deW + (size_t)it * DD * DD, deb + (size_t)it * DD, y_, NTOK, DD, DD, 3, mem_);

        // ---- temporal encoder block (rows = m*62+t, same flat buffer) ----
        GEMM(y_, tWqkv + (size_t)it * 3 * DD * DD, tbqkv + (size_t)it * 3 * DD,
             qkv_, NTOK, 384, DD, 0);
        {
            dim3 grid(BB * VV, HH);
            temporal_attn_kernel<<<grid, 128>>>(qkv_, a_);
        }
        // Wo + residual(y) + LN1 -> y1  (fused)
        GEMM(a_, tWo + (size_t)it * DD * DD, tbo + (size_t)it * DD, y1_, NTOK, DD, DD, 4,
             nullptr, y_, tln1g + it * DD, tln1b + it * DD);
        GEMM(y1_, tW1 + (size_t)it * HDm * DD, tb1 + (size_t)it * HDm, h_, NTOK, HDm, DD, 1);
        // W2 + residual(y1) + LN2 + mem -> y  (fused)
        GEMM(h_, tW2 + (size_t)it * DD * HDm, tb2 + (size_t)it * DD, y_, NTOK, DD, HDm, 5,
             nullptr, y1_, tln2g + it * DD, tln2b + it * DD, mem_);
    }

    // out = leakyrelu(y @ W_out^T)
    GEMM(y_, W_out, nullptr, out, NTOK, 64, DD, 2);
}

// round 6
// speedup vs baseline: 1.1813x; 1.1120x over previous
#include <cuda_runtime.h>
#include <math.h>
#include <stdint.h>

typedef unsigned long long u64;

// Problem constants
#define BB   16
#define CC   32
#define TT   62
#define VV   19
#define DD   128
#define HH   8
#define HDm  256
#define NBT  (BB*TT)      // 992
#define NTOK (NBT*VV)     // 18848
#define NPAIR (VV*VV)     // 361

// ---------------- scratch buffers ----------------
__device__ float d_p   [NTOK*CC];
__device__ float d_y   [NTOK*DD];
__device__ float d_e   [NTOK*HDm];
__device__ float d_bias[NBT*NPAIR*HH];
__device__ float d_qkv [NTOK*384];
__device__ float d_a   [NTOK*DD];
__device__ float d_y1  [NTOK*DD];
__device__ float d_h   [NTOK*HDm];
__device__ float d_f   [NTOK*DD];
__device__ float d_mem [NTOK*DD];
__device__ float d_pe  [TT*DD];

// ---------------- packed f32x2 helpers ----------------
__device__ __forceinline__ u64 pack_dup(float x) {
    u64 r; asm("mov.b64 %0, {%1, %1};" : "=l"(r) : "f"(x)); return r;
}
__device__ __forceinline__ void ffma2(u64& d, u64 a, u64 b) {
    asm("fma.rn.f32x2 %0, %1, %2, %3;" : "=l"(d) : "l"(a), "l"(b), "l"(d));
}
__device__ __forceinline__ float2 unpack2(u64 v) {
    float2 f; asm("mov.b64 {%0, %1}, %2;" : "=f"(f.x), "=f"(f.y) : "l"(v)); return f;
}

// ---------------- p builder: pose [B,C,T,V] -> p [B,T,V,C] ----------------
__global__ void build_p_kernel(const float* __restrict__ pose) {
    int idx = blockIdx.x * 256 + threadIdx.x;
    if (idx >= NTOK * CC) return;
    int c  = idx & 31;
    int v  = (idx >> 5) % VV;
    int bt = idx / (CC * VV);
    int b = bt / TT, t = bt % TT;
    d_p[idx] = pose[(((size_t)b * CC + c) * TT + t) * VV + v];
}

// ---------------- positional encoding ----------------
__global__ void build_pe_kernel() {
    int t = blockIdx.x, c = threadIdx.x;
    int i2 = c & ~1;
    float div = expf((float)i2 * (-9.210340371976184f / 128.f));
    float ang = (float)t * div;
    d_pe[t * DD + c] = (c & 1) ? cosf(ang) : sinf(ang);
}

// ---------------- 128x128x16 double-buffered SGEMM (FFMA2 inner product) ----------------
// C = act(A[M,K] @ W[N,K]^T + bias)
// act 0: none; 1: relu; 2: leakyrelu(0.01); 3: += pe[row%62][col], write C and C2 (N==128)
#define BM 128
#define BN 128
#define BKg 16
#define APAD 132

__global__ __launch_bounds__(256, 2)
void gemm128_kernel(const float* __restrict__ A, const float* __restrict__ W,
                    const float* __restrict__ bias, float* __restrict__ C,
                    float* __restrict__ C2,
                    int M, int N, int K, int act)
{
    __shared__ float As[2][BKg][APAD];
    __shared__ float Bs[2][BKg][APAD];
    int tid = threadIdx.x;
    int m0 = blockIdx.x * BM;
    int n0 = blockIdx.y * BN;
    int wid = tid >> 5, lane = tid & 31;
    // warp tile 64x32; lane grid 8x4; thread tile 8x8
    int tm = (wid & 1) * 64 + (lane >> 2) * 8;
    int tn = (wid >> 1) * 32 + (lane & 3) * 8;

    int row0 = tid >> 2,         kq0 = (tid & 3) * 4;
    int row1 = (tid + 256) >> 2, kq1 = ((tid + 256) & 3) * 4;

    float4 pa0, pa1, pb0, pb1;
    u64 acc[8][4];
    #pragma unroll
    for (int i = 0; i < 8; i++)
        #pragma unroll
        for (int j = 0; j < 4; j++) acc[i][j] = 0ull;

    const int nk = K / BKg;

    {
        pa0 = (m0 + row0 < M) ? *(const float4*)(A + (size_t)(m0 + row0) * K + kq0)
                              : make_float4(0.f, 0.f, 0.f, 0.f);
        pa1 = (m0 + row1 < M) ? *(const float4*)(A + (size_t)(m0 + row1) * K + kq1)
                              : make_float4(0.f, 0.f, 0.f, 0.f);
        pb0 = (n0 + row0 < N) ? *(const float4*)(W + (size_t)(n0 + row0) * K + kq0)
                              : make_float4(0.f, 0.f, 0.f, 0.f);
        pb1 = (n0 + row1 < N) ? *(const float4*)(W + (size_t)(n0 + row1) * K + kq1)
                              : make_float4(0.f, 0.f, 0.f, 0.f);
        As[0][kq0+0][row0] = pa0.x; As[0][kq0+1][row0] = pa0.y;
        As[0][kq0+2][row0] = pa0.z; As[0][kq0+3][row0] = pa0.w;
        As[0][kq1+0][row1] = pa1.x; As[0][kq1+1][row1] = pa1.y;
        As[0][kq1+2][row1] = pa1.z; As[0][kq1+3][row1] = pa1.w;
        Bs[0][kq0+0][row0] = pb0.x; Bs[0][kq0+1][row0] = pb0.y;
        Bs[0][kq0+2][row0] = pb0.z; Bs[0][kq0+3][row0] = pb0.w;
        Bs[0][kq1+0][row1] = pb1.x; Bs[0][kq1+1][row1] = pb1.y;
        Bs[0][kq1+2][row1] = pb1.z; Bs[0][kq1+3][row1] = pb1.w;
    }
    __syncthreads();

    for (int kt = 0; kt < nk; kt++) {
        int cur = kt & 1;
        if (kt + 1 < nk) {
            int k0 = (kt + 1) * BKg;
            pa0 = (m0 + row0 < M) ? *(const float4*)(A + (size_t)(m0 + row0) * K + k0 + kq0)
                                  : make_float4(0.f, 0.f, 0.f, 0.f);
            pa1 = (m0 + row1 < M) ? *(const float4*)(A + (size_t)(m0 + row1) * K + k0 + kq1)
                                  : make_float4(0.f, 0.f, 0.f, 0.f);
            pb0 = (n0 + row0 < N) ? *(const float4*)(W + (size_t)(n0 + row0) * K + k0 + kq0)
                                  : make_float4(0.f, 0.f, 0.f, 0.f);
            pb1 = (n0 + row1 < N) ? *(const float4*)(W + (size_t)(n0 + row1) * K + k0 + kq1)
                                  : make_float4(0.f, 0.f, 0.f, 0.f);
        }
        #pragma unroll
        for (int k = 0; k < BKg; k++) {
            float4 a0 = *(const float4*)&As[cur][k][tm];
            float4 a1 = *(const float4*)&As[cur][k][tm + 4];
            ulonglong2 bq0 = *(const ulonglong2*)&Bs[cur][k][tn];
            ulonglong2 bq1 = *(const ulonglong2*)&Bs[cur][k][tn + 4];
            u64 bp[4] = {bq0.x, bq0.y, bq1.x, bq1.y};
            u64 ap[8];
            ap[0] = pack_dup(a0.x); ap[1] = pack_dup(a0.y);
            ap[2] = pack_dup(a0.z); ap[3] = pack_dup(a0.w);
            ap[4] = pack_dup(a1.x); ap[5] = pack_dup(a1.y);
            ap[6] = pack_dup(a1.z); ap[7] = pack_dup(a1.w);
            #pragma unroll
            for (int i = 0; i < 8; i++)
                #pragma unroll
                for (int j = 0; j < 4; j++) ffma2(acc[i][j], ap[i], bp[j]);
        }
        if (kt + 1 < nk) {
            int nb = cur ^ 1;
            As[nb][kq0+0][row0] = pa0.x; As[nb][kq0+1][row0] = pa0.y;
            As[nb][kq0+2][row0] = pa0.z; As[nb][kq0+3][row0] = pa0.w;
            As[nb][kq1+0][row1] = pa1.x; As[nb][kq1+1][row1] = pa1.y;
            As[nb][kq1+2][row1] = pa1.z; As[nb][kq1+3][row1] = pa1.w;
            Bs[nb][kq0+0][row0] = pb0.x; Bs[nb][kq0+1][row0] = pb0.y;
            Bs[nb][kq0+2][row0] = pb0.z; Bs[nb][kq0+3][row0] = pb0.w;
            Bs[nb][kq1+0][row1] = pb1.x; Bs[nb][kq1+1][row1] = pb1.y;
            Bs[nb][kq1+2][row1] = pb1.z; Bs[nb][kq1+3][row1] = pb1.w;
            __syncthreads();
        }
    }

    bool fullN = (n0 + BN <= N);
    #pragma unroll
    for (int i = 0; i < 8; i++) {
        int row = m0 + tm + i;
        if (row >= M) continue;
        float bvals[8];
        #pragma unroll
        for (int jp = 0; jp < 4; jp++) {
            float2 f = unpack2(acc[i][jp]);
            bvals[jp*2]   = f.x;
            bvals[jp*2+1] = f.y;
        }
        #pragma unroll
        for (int j = 0; j < 8; j++) {
            int col = n0 + tn + j;
            float v = bvals[j];
            if (bias && (fullN || col < N)) v += bias[col];
            if (act == 1) v = fmaxf(v, 0.f);
            else if (act == 2) v = (v >= 0.f) ? v : 0.01f * v;
            else if (act == 3) v += d_pe[(row % TT) * DD + ((n0 + tn + j) & 127)];
            bvals[j] = v;
        }
        if (fullN) {
            float* cp = C + (size_t)row * N + n0 + tn;
            *(float4*)(cp)     = make_float4(bvals[0], bvals[1], bvals[2], bvals[3]);
            *(float4*)(cp + 4) = make_float4(bvals[4], bvals[5], bvals[6], bvals[7]);
            if (act == 3) {
                float* c2 = C2 + (size_t)row * N + n0 + tn;
                *(float4*)(c2)     = make_float4(bvals[0], bvals[1], bvals[2], bvals[3]);
                *(float4*)(c2 + 4) = make_float4(bvals[4], bvals[5], bvals[6], bvals[7]);
            }
        } else {
            #pragma unroll
            for (int j = 0; j < 8; j++) {
                int col = n0 + tn + j;
                if (col < N) {
                    C[(size_t)row * N + col] = bvals[j];
                    if (act == 3) C2[(size_t)row * N + col] = bvals[j];
                }
            }
        }
    }
}

// ---------------- fused pairwise bias ----------------
__global__ __launch_bounds__(256)
void bias_kernel(const float* __restrict__ E, const float* __restrict__ WB,
                 const float* __restrict__ prelu_a, int iter, float* __restrict__ OUT)
{
    __shared__ float es[VV * HDm];
    __shared__ float wb[HH * HDm];
    int bt = blockIdx.x;
    int tid = threadIdx.x;
    for (int idx = tid; idx < VV * HDm; idx += 256)
        es[idx] = E[((size_t)bt * VV) * HDm + idx];
    for (int idx = tid; idx < HH * HDm; idx += 256)
        wb[idx] = WB[idx];
    float aP = prelu_a[iter];
    __syncthreads();

    int warp = tid >> 5, lane = tid & 31;
    for (int pr = warp; pr < NPAIR; pr += 8) {
        int vi = pr / VV, vj = pr % VV;
        float acc[8] = {0,0,0,0,0,0,0,0};
        #pragma unroll
        for (int u = 0; u < 8; u++) {
            int k = u * 32 + lane;
            float hv = es[vj * HDm + k] - es[vi * HDm + k];
            hv = (hv >= 0.f) ? hv : aP * hv;
            #pragma unroll
            for (int g = 0; g < 8; g++) acc[g] += hv * wb[g * HDm + k];
        }
        #pragma unroll
        for (int g = 0; g < 8; g++)
            #pragma unroll
            for (int o = 16; o; o >>= 1)
                acc[g] += __shfl_xor_sync(0xffffffffu, acc[g], o);
        if (lane == 0) {
            float* o = OUT + (((size_t)bt * VV + vi) * VV + vj) * HH;
            #pragma unroll
            for (int g = 0; g < 8; g++) o[g] = acc[g] * 0.3535533906f;
        }
    }
}

// ---------------- graph attention (N=19, per-head bias) ----------------
__global__ __launch_bounds__(256)
void graph_attn_kernel(const float* __restrict__ QKV, const float* __restrict__ BIAS,
                       float* __restrict__ OUT)
{
    __shared__ float qs[VV * DD];
    __shared__ float ks[DD * VV];
    __shared__ float vs[DD * VV];
    int bt = blockIdx.x;
    int tid = threadIdx.x;
    for (int idx = tid; idx < VV * DD; idx += 256) {
        int n = idx >> 7, c = idx & 127;
        const float* row = QKV + (size_t)(bt * VV + n) * 384;
        qs[idx] = row[c];
        ks[c * VV + n] = row[128 + c];
        vs[c * VV + n] = row[256 + c];
    }
    __syncthreads();
    int h = tid >> 5, lane = tid & 31;
    for (int i = 0; i < VV; i++) {
        float sc = -1e30f;
        if (lane < VV) {
            float acc = 0.f;
            #pragma unroll
            for (int c = 0; c < 16; c++)
                acc += qs[i * DD + h * 16 + c] * ks[(h * 16 + c) * VV + lane];
            sc = acc * 0.25f + BIAS[(((size_t)bt * VV + i) * VV + lane) * HH + h];
        }
        float mx = sc;
        #pragma unroll
        for (int o = 16; o; o >>= 1) mx = fmaxf(mx, __shfl_xor_sync(0xffffffffu, mx, o));
        float ev = (lane < VV) ? __expf(sc - mx) : 0.f;
        float sum = ev;
        #pragma unroll
        for (int o = 16; o; o >>= 1) sum += __shfl_xor_sync(0xffffffffu, sum, o);
        float aj = ev / sum;
        float o_acc = 0.f;
        int cc = lane & 15;
        #pragma unroll
        for (int j = 0; j < VV; j++) {
            float aw = __shfl_sync(0xffffffffu, aj, j);
            o_acc += aw * vs[(h * 16 + cc) * VV + j];
        }
        if (lane < 16) OUT[(size_t)(bt * VV + i) * DD + h * 16 + lane] = o_acc;
    }
}

// ---------------- temporal attention (N=62, no bias) ----------------
__global__ __launch_bounds__(128)
void temporal_attn_kernel(const float* __restrict__ QKV, float* __restrict__ OUT)
{
    __shared__ float ks[16 * 65];
    __shared__ float vs[16 * 65];
    int bn = blockIdx.x, h = blockIdx.y;
    int tid = threadIdx.x;
    for (int idx = tid; idx < 16 * 64; idx += 128) {
        int c = idx >> 6, n = idx & 63;
        float kv = 0.f, vv = 0.f;
        if (n < TT) {
            const float* row = QKV + (size_t)(bn * TT + n) * 384 + h * 16 + c;
            kv = row[128];
            vv = row[256];
        }
        ks[c * 65 + n] = kv;
        vs[c * 65 + n] = vv;
    }
    __syncthreads();
    int warp = tid >> 5, lane = tid & 31;
    for (int i = warp; i < TT; i += 4) {
        float q = (lane < 16) ? QKV[(size_t)(bn * TT + i) * 384 + h * 16 + lane] : 0.f;
        float s0 = 0.f, s1 = 0.f;
        #pragma unroll
        for (int c = 0; c < 16; c++) {
            float qc = __shfl_sync(0xffffffffu, q, c);
            s0 += qc * ks[c * 65 + lane];
            s1 += qc * ks[c * 65 + lane + 32];
        }
        s0 *= 0.25f; s1 *= 0.25f;
        bool v1 = (lane + 32) < TT;
        float mx = fmaxf(s0, v1 ? s1 : -1e30f);
        #pragma unroll
        for (int o = 16; o; o >>= 1) mx = fmaxf(mx, __shfl_xor_sync(0xffffffffu, mx, o));
        float e0 = __expf(s0 - mx);
        float e1 = v1 ? __expf(s1 - mx) : 0.f;
        float sum = e0 + e1;
        #pragma unroll
        for (int o = 16; o; o >>= 1) sum += __shfl_xor_sync(0xffffffffu, sum, o);
        float inv = 1.f / sum;
        e0 *= inv; e1 *= inv;
        float o_acc = 0.f;
        int cc = lane & 15;
        #pragma unroll
        for (int j = 0; j < 32; j++) {
            float aw = __shfl_sync(0xffffffffu, e0, j);
            o_acc += aw * vs[cc * 65 + j];
        }
        #pragma unroll
        for (int j = 32; j < TT; j++) {
            float aw = __shfl_sync(0xffffffffu, e1, j - 32);
            o_acc += aw * vs[cc * 65 + j];
        }
        if (lane < 16) OUT[(size_t)(bn * TT + i) * DD + h * 16 + lane] = o_acc;
    }
}

// ---------------- LayerNorm: out = LN(X + R) * g + b (+ ADD) ----------------
__global__ __launch_bounds__(256)
void ln_kernel(const float* __restrict__ X, const float* __restrict__ R,
               const float* __restrict__ g, const float* __restrict__ b,
               float* __restrict__ OUT, const float* __restrict__ ADD)
{
    int warp = threadIdx.x >> 5, lane = threadIdx.x & 31;
    int row = blockIdx.x * 8 + warp;
    if (row >= NTOK) return;
    const float* x = X + (size_t)row * DD;
    const float* r = R + (size_t)row * DD;
    float v[4];
    #pragma unroll
    for (int u = 0; u < 4; u++) v[u] = x[lane + u * 32] + r[lane + u * 32];
    float s = v[0] + v[1] + v[2] + v[3];
    #pragma unroll
    for (int o = 16; o; o >>= 1) s += __shfl_xor_sync(0xffffffffu, s, o);
    float m = s * (1.f / 128.f);
    float sv = 0.f;
    #pragma unroll
    for (int u = 0; u < 4; u++) { float dlt = v[u] - m; sv += dlt * dlt; }
    #pragma unroll
    for (int o = 16; o; o >>= 1) sv += __shfl_xor_sync(0xffffffffu, sv, o);
    float rinv = rsqrtf(sv * (1.f / 128.f) + 1e-5f);
    #pragma unroll
    for (int u = 0; u < 4; u++) {
        int c = lane + u * 32;
        float o = (v[u] - m) * rinv * g[c] + b[c];
        if (ADD) o += ADD[(size_t)row * DD + c];
        OUT[(size_t)row * DD + c] = o;
    }
}

// ---------------- host launcher ----------------
static void GEMM(const float* A, const float* W, const float* bias, float* C,
                 int M, int N, int K, int act, float* C2 = nullptr)
{
    dim3 grid((M + BM - 1) / BM, (N + BN - 1) / BN);
    gemm128_kernel<<<grid, 256>>>(A, W, bias, C, C2, M, N, K, act);
}

extern "C" void kernel_launch(void* const* d_in, const int* in_sizes, int n_in,
                              void* d_out, int out_size)
{
    const float* pose    = (const float*)d_in[0];
    const float* W_pose  = (const float*)d_in[1];
    const float* W_emb   = (const float*)d_in[2];
    const float* prelu_a = (const float*)d_in[3];
    const float* W_bias  = (const float*)d_in[4];
    const float* gWqkv   = (const float*)d_in[5];
    const float* gbqkv   = (const float*)d_in[6];
    const float* gWo     = (const float*)d_in[7];
    const float* gbo     = (const float*)d_in[8];
    const float* gln1g   = (const float*)d_in[9];
    const float* gln1b   = (const float*)d_in[10];
    const float* gW1     = (const float*)d_in[11];
    const float* gb1     = (const float*)d_in[12];
    const float* gW2     = (const float*)d_in[13];
    const float* gb2     = (const float*)d_in[14];
    const float* gln2g   = (const float*)d_in[15];
    const float* gln2b   = (const float*)d_in[16];
    const float* deW     = (const float*)d_in[17];
    const float* deb     = (const float*)d_in[18];
    const float* tWqkv   = (const float*)d_in[19];
    const float* tbqkv   = (const float*)d_in[20];
    const float* tWo     = (const float*)d_in[21];
    const float* tbo     = (const float*)d_in[22];
    const float* tln1g   = (const float*)d_in[23];
    const float* tln1b   = (const float*)d_in[24];
    const float* tW1     = (const float*)d_in[25];
    const float* tb1     = (const float*)d_in[26];
    const float* tW2     = (const float*)d_in[27];
    const float* tb2     = (const float*)d_in[28];
    const float* tln2g   = (const float*)d_in[29];
    const float* tln2b   = (const float*)d_in[30];
    const float* W_out   = (const float*)d_in[31];
    float* out = (float*)d_out;

    float *p_, *y_, *e_, *bias_, *qkv_, *a_, *y1_, *h_, *f_, *mem_;
    cudaGetSymbolAddress((void**)&p_,    d_p);
    cudaGetSymbolAddress((void**)&y_,    d_y);
    cudaGetSymbolAddress((void**)&e_,    d_e);
    cudaGetSymbolAddress((void**)&bias_, d_bias);
    cudaGetSymbolAddress((void**)&qkv_,  d_qkv);
    cudaGetSymbolAddress((void**)&a_,    d_a);
    cudaGetSymbolAddress((void**)&y1_,   d_y1);
    cudaGetSymbolAddress((void**)&h_,    d_h);
    cudaGetSymbolAddress((void**)&f_,    d_f);
    cudaGetSymbolAddress((void**)&mem_,  d_mem);

    build_p_kernel<<<(NTOK * CC + 255) / 256, 256>>>(pose);
    build_pe_kernel<<<TT, DD>>>();
    GEMM(p_, W_pose, nullptr, y_, NTOK, DD, CC, 0);

    for (int it = 0; it < 2; it++) {
        // ---- pairwise bias (linear-in-diff trick) ----
        GEMM(p_, W_emb + (size_t)it * HDm * CC, nullptr, e_, NTOK, HDm, CC, 0);
        bias_kernel<<<NBT, 256>>>(e_, W_bias + (size_t)it * HH * HDm, prelu_a, it, bias_);

        // ---- graph encoder block (rows = bt*19+v) ----
        GEMM(y_, gWqkv + (size_t)it * 3 * DD * DD, gbqkv + (size_t)it * 3 * DD,
             qkv_, NTOK, 384, DD, 0);
        graph_attn_kernel<<<NBT, 256>>>(qkv_, bias_, a_);
        GEMM(a_, gWo + (size_t)it * DD * DD, gbo + (size_t)it * DD, f_, NTOK, DD, DD, 0);
        ln_kernel<<<(NTOK + 7) / 8, 256>>>(f_, y_, gln1g + it * DD, gln1b + it * DD, y1_, nullptr);
        GEMM(y1_, gW1 + (size_t)it * HDm * DD, gb1 + (size_t)it * HDm, h_, NTOK, HDm, DD, 1);
        GEMM(h_, gW2 + (size_t)it * DD * HDm, gb2 + (size_t)it * DD, f_, NTOK, DD, HDm, 0);
        ln_kernel<<<(NTOK + 7) / 8, 256>>>(f_, y1_, gln2g + it * DD, gln2b + it * DD, a_, nullptr);
        // de linear + pe -> y and mem
        GEMM(a_, deW + (size_t)it * DD * DD, deb + (size_t)it * DD, y_, NTOK, DD, DD, 3, mem_);

        // ---- temporal encoder block (rows = m*62+t) ----
        GEMM(y_, tWqkv + (size_t)it * 3 * DD * DD, tbqkv + (size_t)it * 3 * DD,
             qkv_, NTOK, 384, DD, 0);
        {
            dim3 grid(BB * VV, HH);
            temporal_attn_kernel<<<grid, 128>>>(qkv_, a_);
        }
        GEMM(a_, tWo + (size_t)it * DD * DD, tbo + (size_t)it * DD, f_, NTOK, DD, DD, 0);
        ln_kernel<<<(NTOK + 7) / 8, 256>>>(f_, y_, tln1g + it * DD, tln1b + it * DD, y1_, nullptr);
        GEMM(y1_, tW1 + (size_t)it * HDm * DD, tb1 + (size_t)it * HDm, h_, NTOK, HDm, DD, 1);
        GEMM(h_, tW2 + (size_t)it * DD * HDm, tb2 + (size_t)it * DD, f_, NTOK, DD, HDm, 0);
        ln_kernel<<<(NTOK + 7) / 8, 256>>>(f_, y1_, tln2g + it * DD, tln2b + it * DD, y_, mem_);
    }

    // out = leakyrelu(y @ W_out^T)
    GEMM(y_, W_out, nullptr, out, NTOK, 64, DD, 2);
}